// round 5
// baseline (speedup 1.0000x reference)
#include <cuda_runtime.h>
#include <math.h>
#include <stdint.h>

#define BB 64
#define NN 4096
#define DD 128
#define SS 65536
#define KTOP 16

typedef unsigned long long ull;

// ---------------- scratch (device globals; allocation-free) ----------------
__device__ float g_mt[(size_t)DD * SS];  // normalized memory^T: [d][s]   (32 MB)
__device__ float g_qpart[BB * 2 * DD];   // per-CTA partial gelu sums
__device__ float g_qt[DD * BB];          // normalized q^T: [d][b]
__device__ float g_sim[(size_t)BB * SS]; // cosine sims                    (16 MB)
__device__ float g_proto[BB * DD];

// ---------------- generic helpers ----------------
__device__ __forceinline__ ull ffma2(ull a, ull b, ull c) {
    ull d;
    asm("fma.rn.f32x2 %0, %1, %2, %3;" : "=l"(d) : "l"(a), "l"(b), "l"(c));
    return d;
}
__device__ __forceinline__ ull dup2(float x) {
    ull d;
    asm("mov.b64 %0, {%1, %1};" : "=l"(d) : "f"(x));
    return d;
}
__device__ __forceinline__ void unpack2(ull v, float& lo, float& hi) {
    asm("mov.b64 {%0, %1}, %2;" : "=f"(lo), "=f"(hi) : "l"(v));
}
__device__ __forceinline__ float gelu_exact(float z) {
    return 0.5f * z * (1.0f + erff(z * 0.70710678118654752f));
}
__device__ __forceinline__ float tf32r(float x) {
    float y;
    asm("cvt.rna.tf32.f32 %0, %1;" : "=f"(y) : "f"(x));
    return y;
}
__device__ __forceinline__ uint32_t smem_u32(const void* p) {
    uint32_t a;
    asm("{ .reg .u64 t; cvta.to.shared.u64 t, %1; cvt.u32.u64 %0, t; }" : "=r"(a) : "l"(p));
    return a;
}
__device__ __forceinline__ void cpa16(uint32_t dst, const void* src) {
    asm volatile("cp.async.cg.shared.global [%0], [%1], 16;" :: "r"(dst), "l"(src));
}
#define CP_COMMIT() asm volatile("cp.async.commit_group;" ::: "memory")

// tf32 m16n8k8 mma.sync (portable PTX; lowers to HMMA fallback on sm_103)
__device__ __forceinline__ void mma_tf32(float* c, uint32_t a0, uint32_t a1,
                                         uint32_t a2, uint32_t a3,
                                         uint32_t b0, uint32_t b1) {
    asm volatile(
        "mma.sync.aligned.m16n8k8.row.col.f32.tf32.tf32.f32 "
        "{%0,%1,%2,%3}, {%4,%5,%6,%7}, {%8,%9}, {%0,%1,%2,%3};"
        : "+f"(c[0]), "+f"(c[1]), "+f"(c[2]), "+f"(c[3])
        : "r"(a0), "r"(a1), "r"(a2), "r"(a3), "r"(b0), "r"(b1));
}

// ---------------- K2: tf32 mma.sync conv1d+GeLU+sum-over-n --------------
// 128 CTAs: cta = (b, half). Each does 16 tiles of 128 positions.
// Single-pass tf32 W (rna-rounded). 4-stage cp.async ring, 1 sync/step.
#define WSTR 132
#define ASTR 68
#define ABUF 8704                    // 128 * 68 floats
#define F_WHI  0
#define F_A    16896
#define F_BIAS 51712
#define F_RED  51840
#define K2_SMEM ((51840 + 256) * 4)  // 208384 bytes

__global__ void __launch_bounds__(256, 1) k2_mma(const float* __restrict__ x,
                                                 const float* __restrict__ w,
                                                 const float* __restrict__ bias) {
    extern __shared__ float sm[];
    float* ws_hi = sm + F_WHI;
    float* sbias = sm + F_BIAS;
    float* red   = sm + F_RED;
    uint32_t aB = smem_u32(sm + F_A);

    int tid = threadIdx.x, wid = tid >> 5, lane = tid & 31;
    int g = lane >> 2, kc = lane & 3;
    int cta = blockIdx.x, b = cta >> 1, half = cta & 1;
    const float* xb = x + ((size_t)b * NN + (size_t)half * 2048) * DD;

    // ---- stage W (rna-rounded tf32) ----
    for (int i = tid; i < 4096; i += 256) {      // 4096 float4 over [128e][128d]
        float4 v = ((const float4*)w)[i];
        int e = i >> 5, c4 = (i & 31) * 4;
        float4 h;
        h.x = tf32r(v.x); h.y = tf32r(v.y); h.z = tf32r(v.z); h.w = tf32r(v.w);
        *(float4*)&ws_hi[e * WSTR + c4] = h;
    }
    if (tid < 128) sbias[tid] = bias[tid];

    // per-thread fixed e-columns & bias (read after staging sync below)
    int ew = (wid & 3) * 32;             // warp e base

    float c[4][4][4];
    #pragma unroll
    for (int mf = 0; mf < 4; ++mf)
        #pragma unroll
        for (int ef = 0; ef < 4; ++ef)
            #pragma unroll
            for (int q = 0; q < 4; ++q) c[mf][ef][q] = 0.f;
    float es[8];
    #pragma unroll
    for (int s = 0; s < 8; ++s) es[s] = 0.f;

    // ---- cp.async loader: global k-half gstep into ring buffer buf ----
    auto issue_load = [&](int gstep, int buf) {
        int t = gstep >> 1, h = gstep & 1;
        const float* base = xb + (size_t)t * (128 * DD) + h * 64;
        uint32_t dst0 = aB + (uint32_t)buf * (ABUF * 4);
        #pragma unroll
        for (int j = 0; j < 8; ++j) {
            int idx = j * 256 + tid;             // 0..2047
            int row = idx >> 4, seg = idx & 15;
            cpa16(dst0 + (uint32_t)(row * ASTR + seg * 4) * 4,
                  base + (size_t)row * DD + seg * 4);
        }
    };

    issue_load(0, 0); CP_COMMIT();
    issue_load(1, 1); CP_COMMIT();
    __syncthreads();                 // W staged (also covers bias)

    float bs[8];
    #pragma unroll
    for (int ef = 0; ef < 4; ++ef) {
        bs[ef * 2 + 0] = sbias[ew + ef * 8 + 2 * kc + 0];
        bs[ef * 2 + 1] = sbias[ew + ef * 8 + 2 * kc + 1];
    }

    int mrow = (wid >> 2) * 64 + g;              // A row base (m)

    #pragma unroll 1
    for (int step = 0; step < 32; ++step) {
        if (step < 30) {
            issue_load(step + 2, (step + 2) & 3); CP_COMMIT();
            asm volatile("cp.async.wait_group 2;" ::: "memory");
        } else if (step == 30) {
            asm volatile("cp.async.wait_group 1;" ::: "memory");
        } else {
            asm volatile("cp.async.wait_group 0;" ::: "memory");
        }
        __syncthreads();

        const float* A = sm + F_A + (step & 3) * ABUF;
        int kg0 = (step & 1) * 64;               // global k offset of this half
        #pragma unroll
        for (int ks = 0; ks < 8; ++ks) {
            int k0 = ks * 8 + kc;
            uint32_t a[4][4];
            #pragma unroll
            for (int mf = 0; mf < 4; ++mf) {
                int r = mrow + mf * 16;
                a[mf][0] = __float_as_uint(A[r * ASTR + k0]);
                a[mf][1] = __float_as_uint(A[(r + 8) * ASTR + k0]);
                a[mf][2] = __float_as_uint(A[r * ASTR + k0 + 4]);
                a[mf][3] = __float_as_uint(A[(r + 8) * ASTR + k0 + 4]);
            }
            #pragma unroll
            for (int ef = 0; ef < 4; ++ef) {
                int e = ew + ef * 8 + g;
                uint32_t b0 = __float_as_uint(ws_hi[e * WSTR + kg0 + k0]);
                uint32_t b1 = __float_as_uint(ws_hi[e * WSTR + kg0 + k0 + 4]);
                #pragma unroll
                for (int mf = 0; mf < 4; ++mf)
                    mma_tf32(c[mf][ef], a[mf][0], a[mf][1], a[mf][2], a[mf][3], b0, b1);
            }
        }

        if ((step & 1) == 1) {
            // tile finished: gelu(feat + bias), accumulate over m, reset accums
            #pragma unroll
            for (int mf = 0; mf < 4; ++mf)
                #pragma unroll
                for (int ef = 0; ef < 4; ++ef)
                    #pragma unroll
                    for (int q = 0; q < 4; ++q) {
                        int s = ef * 2 + (q & 1);
                        es[s] += gelu_exact(c[mf][ef][q] + bs[s]);
                        c[mf][ef][q] = 0.f;
                    }
        }
    }

    // ---- reduce over m: shfl across g-groups, then across 2 m-warps ----
    #pragma unroll
    for (int off = 16; off >= 4; off >>= 1)
        #pragma unroll
        for (int s = 0; s < 8; ++s)
            es[s] += __shfl_xor_sync(0xffffffffu, es[s], off);
    __syncthreads();                 // A ring idle; red region safe
    if (g == 0) {
        #pragma unroll
        for (int s = 0; s < 8; ++s) {
            int ecol = ew + (s >> 1) * 8 + 2 * kc + (s & 1);
            red[(wid >> 2) * 128 + ecol] = es[s];
        }
    }
    __syncthreads();
    if (tid < 128)
        g_qpart[(b * 2 + half) * 128 + tid] = red[tid] + red[128 + tid];
}

// ---------------- K1: normalize+transpose memory -> g_mt ----------------
__global__ void __launch_bounds__(256) k1_mt(const float* __restrict__ mem) {
    __shared__ float tile[64][129];
    __shared__ float inv[64];
    int s0 = blockIdx.x * 64;
    int tid = threadIdx.x;

    int c = tid & 31, r0 = tid >> 5;
    #pragma unroll
    for (int it = 0; it < 8; ++it) {
        int r = r0 + it * 8;
        float4 v = *(const float4*)&mem[(size_t)(s0 + r) * 128 + c * 4];
        tile[r][c * 4 + 0] = v.x; tile[r][c * 4 + 1] = v.y;
        tile[r][c * 4 + 2] = v.z; tile[r][c * 4 + 3] = v.w;
    }
    __syncthreads();
    if (tid < 64) {
        float acc = 0.f;
        #pragma unroll 8
        for (int k = 0; k < 128; ++k) { float t = tile[tid][k]; acc = fmaf(t, t, acc); }
        inv[tid] = 1.0f / fmaxf(sqrtf(acc), 1e-12f);
    }
    __syncthreads();
    int r = tid & 63, kg = tid >> 6;
    float iv = inv[r];
    #pragma unroll
    for (int it = 0; it < 32; ++it) {
        int k = kg + it * 4;
        g_mt[(size_t)k * SS + s0 + r] = tile[r][k] * iv;
    }
}

// ---------------- K3: finalize q + normalize + transpose ----------------
__global__ void k3_q() {
    int b = blockIdx.x, e = threadIdx.x;
    float q = g_qpart[b * 256 + e] + g_qpart[b * 256 + 128 + e];
    __shared__ float sr[128];
    sr[e] = q * q;
    __syncthreads();
    for (int off = 64; off; off >>= 1) {
        if (e < off) sr[e] += sr[e + off];
        __syncthreads();
    }
    float inv = 1.0f / fmaxf(sqrtf(sr[0]), 1e-12f);
    g_qt[e * 64 + b] = q * inv;
}

// ---------------- K4: sim = qn @ mn^T (64 x 65536, f32x2) ---------------
// tile 64b x 128s, grid 512, acc 4b x 8s per thread (32 regs).
__global__ void __launch_bounds__(256) k4_sim() {
    __shared__ float qs[128 * 64];   // 32KB
    __shared__ float ms[8 * 128];    // 4KB
    int tid = threadIdx.x;
    int s0 = blockIdx.x * 128;

    for (int i = tid; i < 8192; i += 256) qs[i] = g_qt[i];

    int tm = tid >> 4, tn = tid & 15;
    ull acc[4][4];
    #pragma unroll
    for (int i = 0; i < 4; ++i)
        #pragma unroll
        for (int j = 0; j < 4; ++j) acc[i][j] = 0ull;

    for (int ks = 0; ks < 16; ++ks) {
        __syncthreads();
        {
            int r = tid >> 5, cc = (tid & 31) * 4;
            *(float4*)&ms[r * 128 + cc] =
                *(const float4*)&g_mt[(size_t)(ks * 8 + r) * SS + s0 + cc];
        }
        __syncthreads();
        #pragma unroll
        for (int k = 0; k < 8; ++k) {
            float4 av = *(const float4*)&qs[(ks * 8 + k) * 64 + tm * 4];
            ull a0 = dup2(av.x), a1 = dup2(av.y), a2 = dup2(av.z), a3 = dup2(av.w);
            const float* mrow = ms + k * 128;
            #pragma unroll
            for (int gg = 0; gg < 2; ++gg) {
                ulonglong2 bv = *(const ulonglong2*)(mrow + (tn + gg * 16) * 4);
                acc[0][gg * 2 + 0] = ffma2(a0, bv.x, acc[0][gg * 2 + 0]);
                acc[0][gg * 2 + 1] = ffma2(a0, bv.y, acc[0][gg * 2 + 1]);
                acc[1][gg * 2 + 0] = ffma2(a1, bv.x, acc[1][gg * 2 + 0]);
                acc[1][gg * 2 + 1] = ffma2(a1, bv.y, acc[1][gg * 2 + 1]);
                acc[2][gg * 2 + 0] = ffma2(a2, bv.x, acc[2][gg * 2 + 0]);
                acc[2][gg * 2 + 1] = ffma2(a2, bv.y, acc[2][gg * 2 + 1]);
                acc[3][gg * 2 + 0] = ffma2(a3, bv.x, acc[3][gg * 2 + 0]);
                acc[3][gg * 2 + 1] = ffma2(a3, bv.y, acc[3][gg * 2 + 1]);
            }
        }
    }
    #pragma unroll
    for (int i = 0; i < 4; ++i) {
        int b = tm * 4 + i;
        #pragma unroll
        for (int gg = 0; gg < 2; ++gg) {
            float4 o;
            unpack2(acc[i][gg * 2 + 0], o.x, o.y);
            unpack2(acc[i][gg * 2 + 1], o.z, o.w);
            *(float4*)&g_sim[(size_t)b * SS + s0 + (tn + gg * 16) * 4] = o;
        }
    }
}

// ---------------- K5: top-16 + softmax + proto gather -------------------
__global__ void __launch_bounds__(256) k5_topk(const float* __restrict__ mem) {
    int b = blockIdx.x, tid = threadIdx.x;
    __shared__ float cv[4096];
    __shared__ int   ci[4096];
    __shared__ float rv[256];
    __shared__ int   ri[256];
    __shared__ float selv[KTOP];
    __shared__ int   seli[KTOP];
    __shared__ float attn[KTOP];

    float vs[KTOP]; int is[KTOP];
    #pragma unroll
    for (int j = 0; j < KTOP; ++j) { vs[j] = -1e30f; is[j] = 0; }
    float mn = -1e30f; int mj = 0;

    const float* row = g_sim + (size_t)b * SS;
    for (int s = tid; s < SS; s += 256) {
        float v = row[s];
        if (v > mn) {
            vs[mj] = v; is[mj] = s;
            mn = vs[0]; mj = 0;
            #pragma unroll
            for (int j = 1; j < KTOP; ++j) if (vs[j] < mn) { mn = vs[j]; mj = j; }
        }
    }
    #pragma unroll
    for (int j = 0; j < KTOP; ++j) { cv[tid * KTOP + j] = vs[j]; ci[tid * KTOP + j] = is[j]; }
    __syncthreads();

    for (int r = 0; r < KTOP; ++r) {
        float mv = cv[tid * KTOP]; int mi = tid * KTOP;
        #pragma unroll
        for (int j = 1; j < KTOP; ++j)
            if (cv[tid * KTOP + j] > mv) { mv = cv[tid * KTOP + j]; mi = tid * KTOP + j; }
        rv[tid] = mv; ri[tid] = mi;
        __syncthreads();
        for (int off = 128; off; off >>= 1) {
            if (tid < off && rv[tid + off] > rv[tid]) { rv[tid] = rv[tid + off]; ri[tid] = ri[tid + off]; }
            __syncthreads();
        }
        if (tid == 0) {
            selv[r] = rv[0];
            seli[r] = ci[ri[0]];
            cv[ri[0]] = -1e30f;
        }
        __syncthreads();
    }

    if (tid == 0) {
        float mx = selv[0];
        float e[KTOP], ssum = 0.f;
        #pragma unroll
        for (int k = 0; k < KTOP; ++k) { e[k] = expf(selv[k] - mx); ssum += e[k]; }
        #pragma unroll
        for (int k = 0; k < KTOP; ++k) attn[k] = e[k] / ssum;
    }
    __syncthreads();

    if (tid < 128) {
        float acc = 0.f;
        #pragma unroll
        for (int k = 0; k < KTOP; ++k)
            acc = fmaf(attn[k], mem[(size_t)seli[k] * 128 + tid], acc);
        g_proto[b * 128 + tid] = acc;
    }
}

// ---------------- K6: out = x + scale * proto ---------------------------
__global__ void __launch_bounds__(256) k6_add(const float* __restrict__ x,
                                              const float* __restrict__ scale_p,
                                              float* __restrict__ out) {
    __shared__ float pr[128];
    __shared__ float sc;
    int b = blockIdx.y;
    if (threadIdx.x < 128) pr[threadIdx.x] = g_proto[b * 128 + threadIdx.x];
    if (threadIdx.x == 0) sc = *scale_p;
    __syncthreads();

    float s = sc;
    const float4* xv = (const float4*)x;
    float4* ov = (float4*)out;
    size_t f0 = ((size_t)b * (NN * DD) + (size_t)blockIdx.x * 4096) >> 2;
    #pragma unroll
    for (int it = 0; it < 4; ++it) {
        size_t f = f0 + it * 256 + threadIdx.x;
        float4 v = xv[f];
        int d4 = (int)(f & 31);
        const float* p = &pr[d4 * 4];
        v.x = fmaf(s, p[0], v.x);
        v.y = fmaf(s, p[1], v.y);
        v.z = fmaf(s, p[2], v.z);
        v.w = fmaf(s, p[3], v.w);
        ov[f] = v;
    }
}

// ---------------- launch -------------------------------------------------
extern "C" void kernel_launch(void* const* d_in, const int* in_sizes, int n_in,
                              void* d_out, int out_size) {
    const float* x      = (const float*)d_in[0];
    const float* conv_w = (const float*)d_in[1];
    const float* conv_b = (const float*)d_in[2];
    const float* memory = (const float*)d_in[3];
    const float* scale  = (const float*)d_in[4];
    float* out = (float*)d_out;

    cudaFuncSetAttribute(k2_mma, cudaFuncAttributeMaxDynamicSharedMemorySize, K2_SMEM);

    k2_mma<<<128, 256, K2_SMEM>>>(x, conv_w, conv_b);
    k1_mt<<<SS / 64, 256>>>(memory);
    k3_q<<<BB, 128>>>();
    k4_sim<<<SS / 128, 256>>>();
    k5_topk<<<BB, 256>>>(memory);
    dim3 g6(128, BB);
    k6_add<<<g6, 256>>>(x, scale, out);
    (void)in_sizes; (void)n_in; (void)out_size;
}

// round 6
// speedup vs baseline: 1.1229x; 1.1229x over previous
#include <cuda_runtime.h>
#include <math.h>
#include <stdint.h>

#define BB 64
#define NN 4096
#define DD 128
#define SS 65536
#define KTOP 16

typedef unsigned long long ull;

// ---------------- scratch (device globals; allocation-free) ----------------
__device__ float g_qpart[BB * 2 * DD];   // per-CTA partial gelu sums
__device__ float g_qt[DD * BB];          // normalized q^T: [d][b]
__device__ float g_sim[(size_t)BB * SS]; // cosine sims                    (16 MB)
__device__ float g_proto[BB * DD];

// ---------------- generic helpers ----------------
__device__ __forceinline__ ull ffma2(ull a, ull b, ull c) {
    ull d;
    asm("fma.rn.f32x2 %0, %1, %2, %3;" : "=l"(d) : "l"(a), "l"(b), "l"(c));
    return d;
}
__device__ __forceinline__ ull dup2(float x) {
    ull d;
    asm("mov.b64 %0, {%1, %1};" : "=l"(d) : "f"(x));
    return d;
}
__device__ __forceinline__ void unpack2(ull v, float& lo, float& hi) {
    asm("mov.b64 {%0, %1}, %2;" : "=f"(lo), "=f"(hi) : "l"(v));
}
__device__ __forceinline__ float gelu_exact(float z) {
    return 0.5f * z * (1.0f + erff(z * 0.70710678118654752f));
}
__device__ __forceinline__ float tf32r(float x) {
    float y;
    asm("cvt.rna.tf32.f32 %0, %1;" : "=f"(y) : "f"(x));
    return y;
}
__device__ __forceinline__ uint32_t smem_u32(const void* p) {
    uint32_t a;
    asm("{ .reg .u64 t; cvta.to.shared.u64 t, %1; cvt.u32.u64 %0, t; }" : "=r"(a) : "l"(p));
    return a;
}
__device__ __forceinline__ void cpa16(uint32_t dst, const void* src) {
    asm volatile("cp.async.cg.shared.global [%0], [%1], 16;" :: "r"(dst), "l"(src));
}
#define CP_COMMIT() asm volatile("cp.async.commit_group;" ::: "memory")

// tf32 m16n8k8 mma.sync (portable PTX; lowers to HMMA fallback on sm_103)
__device__ __forceinline__ void mma_tf32(float* c, uint32_t a0, uint32_t a1,
                                         uint32_t a2, uint32_t a3,
                                         uint32_t b0, uint32_t b1) {
    asm volatile(
        "mma.sync.aligned.m16n8k8.row.col.f32.tf32.tf32.f32 "
        "{%0,%1,%2,%3}, {%4,%5,%6,%7}, {%8,%9}, {%0,%1,%2,%3};"
        : "+f"(c[0]), "+f"(c[1]), "+f"(c[2]), "+f"(c[3])
        : "r"(a0), "r"(a1), "r"(a2), "r"(a3), "r"(b0), "r"(b1));
}

// ---------------- K2: tf32 mma.sync conv1d+GeLU+sum-over-n --------------
// 128 CTAs: cta = (b, half). Each does 16 tiles of 128 positions.
// Single-pass tf32 W (rna-rounded). 4-stage cp.async ring, 1 sync/step.
#define WSTR 132
#define ASTR 68
#define ABUF 8704                    // 128 * 68 floats
#define F_WHI  0
#define F_A    16896
#define F_BIAS 51712
#define F_RED  51840
#define K2_SMEM ((51840 + 256) * 4)  // 208384 bytes

__global__ void __launch_bounds__(256, 1) k2_mma(const float* __restrict__ x,
                                                 const float* __restrict__ w,
                                                 const float* __restrict__ bias) {
    extern __shared__ float sm[];
    float* ws_hi = sm + F_WHI;
    float* sbias = sm + F_BIAS;
    float* red   = sm + F_RED;
    uint32_t aB = smem_u32(sm + F_A);

    int tid = threadIdx.x, wid = tid >> 5, lane = tid & 31;
    int g = lane >> 2, kc = lane & 3;
    int cta = blockIdx.x, b = cta >> 1, half = cta & 1;
    const float* xb = x + ((size_t)b * NN + (size_t)half * 2048) * DD;

    // ---- stage W (rna-rounded tf32) ----
    for (int i = tid; i < 4096; i += 256) {      // 4096 float4 over [128e][128d]
        float4 v = ((const float4*)w)[i];
        int e = i >> 5, c4 = (i & 31) * 4;
        float4 h;
        h.x = tf32r(v.x); h.y = tf32r(v.y); h.z = tf32r(v.z); h.w = tf32r(v.w);
        *(float4*)&ws_hi[e * WSTR + c4] = h;
    }
    if (tid < 128) sbias[tid] = bias[tid];

    int ew = (wid & 3) * 32;             // warp e base

    float c[4][4][4];
    #pragma unroll
    for (int mf = 0; mf < 4; ++mf)
        #pragma unroll
        for (int ef = 0; ef < 4; ++ef)
            #pragma unroll
            for (int q = 0; q < 4; ++q) c[mf][ef][q] = 0.f;
    float es[8];
    #pragma unroll
    for (int s = 0; s < 8; ++s) es[s] = 0.f;

    // ---- cp.async loader: global k-half gstep into ring buffer buf ----
    auto issue_load = [&](int gstep, int buf) {
        int t = gstep >> 1, h = gstep & 1;
        const float* base = xb + (size_t)t * (128 * DD) + h * 64;
        uint32_t dst0 = aB + (uint32_t)buf * (ABUF * 4);
        #pragma unroll
        for (int j = 0; j < 8; ++j) {
            int idx = j * 256 + tid;             // 0..2047
            int row = idx >> 4, seg = idx & 15;
            cpa16(dst0 + (uint32_t)(row * ASTR + seg * 4) * 4,
                  base + (size_t)row * DD + seg * 4);
        }
    };

    issue_load(0, 0); CP_COMMIT();
    issue_load(1, 1); CP_COMMIT();
    __syncthreads();                 // W staged (also covers bias)

    float bs[8];
    #pragma unroll
    for (int ef = 0; ef < 4; ++ef) {
        bs[ef * 2 + 0] = sbias[ew + ef * 8 + 2 * kc + 0];
        bs[ef * 2 + 1] = sbias[ew + ef * 8 + 2 * kc + 1];
    }

    int mrow = (wid >> 2) * 64 + g;              // A row base (m)

    #pragma unroll 1
    for (int step = 0; step < 32; ++step) {
        if (step < 30) {
            issue_load(step + 2, (step + 2) & 3); CP_COMMIT();
            asm volatile("cp.async.wait_group 2;" ::: "memory");
        } else if (step == 30) {
            asm volatile("cp.async.wait_group 1;" ::: "memory");
        } else {
            asm volatile("cp.async.wait_group 0;" ::: "memory");
        }
        __syncthreads();

        const float* A = sm + F_A + (step & 3) * ABUF;
        int kg0 = (step & 1) * 64;               // global k offset of this half
        #pragma unroll
        for (int ks = 0; ks < 8; ++ks) {
            int k0 = ks * 8 + kc;
            uint32_t a[4][4];
            #pragma unroll
            for (int mf = 0; mf < 4; ++mf) {
                int r = mrow + mf * 16;
                a[mf][0] = __float_as_uint(A[r * ASTR + k0]);
                a[mf][1] = __float_as_uint(A[(r + 8) * ASTR + k0]);
                a[mf][2] = __float_as_uint(A[r * ASTR + k0 + 4]);
                a[mf][3] = __float_as_uint(A[(r + 8) * ASTR + k0 + 4]);
            }
            #pragma unroll
            for (int ef = 0; ef < 4; ++ef) {
                int e = ew + ef * 8 + g;
                uint32_t b0 = __float_as_uint(ws_hi[e * WSTR + kg0 + k0]);
                uint32_t b1 = __float_as_uint(ws_hi[e * WSTR + kg0 + k0 + 4]);
                #pragma unroll
                for (int mf = 0; mf < 4; ++mf)
                    mma_tf32(c[mf][ef], a[mf][0], a[mf][1], a[mf][2], a[mf][3], b0, b1);
            }
        }

        if ((step & 1) == 1) {
            #pragma unroll
            for (int mf = 0; mf < 4; ++mf)
                #pragma unroll
                for (int ef = 0; ef < 4; ++ef)
                    #pragma unroll
                    for (int q = 0; q < 4; ++q) {
                        int s = ef * 2 + (q & 1);
                        es[s] += gelu_exact(c[mf][ef][q] + bs[s]);
                        c[mf][ef][q] = 0.f;
                    }
        }
    }

    // ---- reduce over m: shfl across g-groups, then across 2 m-warps ----
    #pragma unroll
    for (int off = 16; off >= 4; off >>= 1)
        #pragma unroll
        for (int s = 0; s < 8; ++s)
            es[s] += __shfl_xor_sync(0xffffffffu, es[s], off);
    __syncthreads();
    if (g == 0) {
        #pragma unroll
        for (int s = 0; s < 8; ++s) {
            int ecol = ew + (s >> 1) * 8 + 2 * kc + (s & 1);
            red[(wid >> 2) * 128 + ecol] = es[s];
        }
    }
    __syncthreads();
    if (tid < 128)
        g_qpart[(b * 2 + half) * 128 + tid] = red[tid] + red[128 + tid];
}

// ---------------- K3: finalize q + normalize + transpose ----------------
__global__ void k3_q() {
    int b = blockIdx.x, e = threadIdx.x;
    float q = g_qpart[b * 256 + e] + g_qpart[b * 256 + 128 + e];
    __shared__ float sr[128];
    sr[e] = q * q;
    __syncthreads();
    for (int off = 64; off; off >>= 1) {
        if (e < off) sr[e] += sr[e + off];
        __syncthreads();
    }
    float inv = 1.0f / fmaxf(sqrtf(sr[0]), 1e-12f);
    g_qt[e * 64 + b] = q * inv;
}

// ---------------- K4f: fused normalize + sim GEMM -----------------------
// Block = 128 s x 64 b. Loads raw memory rows, normalizes+transposes into
// smem, then 128-k f32x2 GEMM. No g_mt global pass.
#define S4_QS  0                     // [128k][64b]   8192
#define S4_MT  8192                  // [128k][128s] 16384
#define S4_TL  24576                 // [64][129]     8256
#define S4_INV 32832                 // [64]
#define K4_SMEM ((32832 + 64) * 4)   // 131584 bytes

__global__ void __launch_bounds__(256, 1) k4f(const float* __restrict__ mem) {
    extern __shared__ float s4[];
    float* qs   = s4 + S4_QS;
    float* mt   = s4 + S4_MT;
    float* tile = s4 + S4_TL;
    float* inv  = s4 + S4_INV;
    int tid = threadIdx.x;
    int s0 = blockIdx.x * 128;

    for (int i = tid; i < 8192; i += 256) qs[i] = g_qt[i];

    #pragma unroll 1
    for (int half = 0; half < 2; ++half) {
        int c = tid & 31, r0 = tid >> 5;
        #pragma unroll
        for (int it = 0; it < 8; ++it) {
            int r = r0 + it * 8;
            float4 v = *(const float4*)&mem[(size_t)(s0 + half * 64 + r) * 128 + c * 4];
            tile[r * 129 + c * 4 + 0] = v.x; tile[r * 129 + c * 4 + 1] = v.y;
            tile[r * 129 + c * 4 + 2] = v.z; tile[r * 129 + c * 4 + 3] = v.w;
        }
        __syncthreads();
        if (tid < 64) {
            float acc = 0.f;
            #pragma unroll 8
            for (int k = 0; k < 128; ++k) { float t = tile[tid * 129 + k]; acc = fmaf(t, t, acc); }
            inv[tid] = 1.0f / fmaxf(sqrtf(acc), 1e-12f);
        }
        __syncthreads();
        int r = tid & 63, kg = tid >> 6;
        float iv = inv[r];
        #pragma unroll
        for (int it = 0; it < 32; ++it) {
            int k = kg + it * 4;
            mt[k * 128 + half * 64 + r] = tile[r * 129 + k] * iv;
        }
        __syncthreads();
    }

    int tm = tid >> 4, tn = tid & 15;
    ull acc[4][4];
    #pragma unroll
    for (int i = 0; i < 4; ++i)
        #pragma unroll
        for (int j = 0; j < 4; ++j) acc[i][j] = 0ull;

    #pragma unroll 8
    for (int k = 0; k < 128; ++k) {
        float4 av = *(const float4*)&qs[k * 64 + tm * 4];
        ull a0 = dup2(av.x), a1 = dup2(av.y), a2 = dup2(av.z), a3 = dup2(av.w);
        const float* mrow = mt + k * 128;
        #pragma unroll
        for (int gg = 0; gg < 2; ++gg) {
            ulonglong2 bv = *(const ulonglong2*)(mrow + (tn + gg * 16) * 4);
            acc[0][gg * 2 + 0] = ffma2(a0, bv.x, acc[0][gg * 2 + 0]);
            acc[0][gg * 2 + 1] = ffma2(a0, bv.y, acc[0][gg * 2 + 1]);
            acc[1][gg * 2 + 0] = ffma2(a1, bv.x, acc[1][gg * 2 + 0]);
            acc[1][gg * 2 + 1] = ffma2(a1, bv.y, acc[1][gg * 2 + 1]);
            acc[2][gg * 2 + 0] = ffma2(a2, bv.x, acc[2][gg * 2 + 0]);
            acc[2][gg * 2 + 1] = ffma2(a2, bv.y, acc[2][gg * 2 + 1]);
            acc[3][gg * 2 + 0] = ffma2(a3, bv.x, acc[3][gg * 2 + 0]);
            acc[3][gg * 2 + 1] = ffma2(a3, bv.y, acc[3][gg * 2 + 1]);
        }
    }
    #pragma unroll
    for (int i = 0; i < 4; ++i) {
        int b = tm * 4 + i;
        #pragma unroll
        for (int gg = 0; gg < 2; ++gg) {
            float4 o;
            unpack2(acc[i][gg * 2 + 0], o.x, o.y);
            unpack2(acc[i][gg * 2 + 1], o.z, o.w);
            *(float4*)&g_sim[(size_t)b * SS + s0 + (tn + gg * 16) * 4] = o;
        }
    }
}

// ---------------- K5: top-16 + softmax + proto gather -------------------
__global__ void __launch_bounds__(256) k5_topk(const float* __restrict__ mem) {
    int b = blockIdx.x, tid = threadIdx.x;
    __shared__ float cv[4096];
    __shared__ int   ci[4096];
    __shared__ float rv[256];
    __shared__ int   ri[256];
    __shared__ float selv[KTOP];
    __shared__ int   seli[KTOP];
    __shared__ float attn[KTOP];

    float vs[KTOP]; int is[KTOP];
    #pragma unroll
    for (int j = 0; j < KTOP; ++j) { vs[j] = -1e30f; is[j] = 0; }
    float mn = -1e30f; int mj = 0;

    const float4* rowv = (const float4*)(g_sim + (size_t)b * SS);
    #pragma unroll 4
    for (int it = 0; it < 64; ++it) {
        int f = it * 256 + tid;
        float4 v = rowv[f];
        float vm = fmaxf(fmaxf(v.x, v.y), fmaxf(v.z, v.w));
        if (vm > mn) {
            float vals[4] = {v.x, v.y, v.z, v.w};
            int sb = f * 4;
            #pragma unroll
            for (int j = 0; j < 4; ++j) {
                if (vals[j] > mn) {
                    vs[mj] = vals[j]; is[mj] = sb + j;
                    mn = vs[0]; mj = 0;
                    #pragma unroll
                    for (int jj = 1; jj < KTOP; ++jj)
                        if (vs[jj] < mn) { mn = vs[jj]; mj = jj; }
                }
            }
        }
    }
    #pragma unroll
    for (int j = 0; j < KTOP; ++j) { cv[tid * KTOP + j] = vs[j]; ci[tid * KTOP + j] = is[j]; }
    __syncthreads();

    for (int r = 0; r < KTOP; ++r) {
        float mv = cv[tid * KTOP]; int mi = tid * KTOP;
        #pragma unroll
        for (int j = 1; j < KTOP; ++j)
            if (cv[tid * KTOP + j] > mv) { mv = cv[tid * KTOP + j]; mi = tid * KTOP + j; }
        rv[tid] = mv; ri[tid] = mi;
        __syncthreads();
        for (int off = 128; off; off >>= 1) {
            if (tid < off && rv[tid + off] > rv[tid]) { rv[tid] = rv[tid + off]; ri[tid] = ri[tid + off]; }
            __syncthreads();
        }
        if (tid == 0) {
            selv[r] = rv[0];
            seli[r] = ci[ri[0]];
            cv[ri[0]] = -1e30f;
        }
        __syncthreads();
    }

    if (tid == 0) {
        float mx = selv[0];
        float e[KTOP], ssum = 0.f;
        #pragma unroll
        for (int k = 0; k < KTOP; ++k) { e[k] = expf(selv[k] - mx); ssum += e[k]; }
        #pragma unroll
        for (int k = 0; k < KTOP; ++k) attn[k] = e[k] / ssum;
    }
    __syncthreads();

    if (tid < 128) {
        float acc = 0.f;
        #pragma unroll
        for (int k = 0; k < KTOP; ++k)
            acc = fmaf(attn[k], mem[(size_t)seli[k] * 128 + tid], acc);
        g_proto[b * 128 + tid] = acc;
    }
}

// ---------------- K6: out = x + scale * proto ---------------------------
__global__ void __launch_bounds__(256) k6_add(const float* __restrict__ x,
                                              const float* __restrict__ scale_p,
                                              float* __restrict__ out) {
    __shared__ float pr[128];
    __shared__ float sc;
    int b = blockIdx.y;
    if (threadIdx.x < 128) pr[threadIdx.x] = g_proto[b * 128 + threadIdx.x];
    if (threadIdx.x == 0) sc = *scale_p;
    __syncthreads();

    float s = sc;
    const float4* xv = (const float4*)x;
    float4* ov = (float4*)out;
    size_t f0 = ((size_t)b * (NN * DD) + (size_t)blockIdx.x * 4096) >> 2;
    #pragma unroll
    for (int it = 0; it < 4; ++it) {
        size_t f = f0 + it * 256 + threadIdx.x;
        float4 v = xv[f];
        int d4 = (int)(f & 31);
        const float* p = &pr[d4 * 4];
        v.x = fmaf(s, p[0], v.x);
        v.y = fmaf(s, p[1], v.y);
        v.z = fmaf(s, p[2], v.z);
        v.w = fmaf(s, p[3], v.w);
        ov[f] = v;
    }
}

// ---------------- launch -------------------------------------------------
extern "C" void kernel_launch(void* const* d_in, const int* in_sizes, int n_in,
                              void* d_out, int out_size) {
    const float* x      = (const float*)d_in[0];
    const float* conv_w = (const float*)d_in[1];
    const float* conv_b = (const float*)d_in[2];
    const float* memory = (const float*)d_in[3];
    const float* scale  = (const float*)d_in[4];
    float* out = (float*)d_out;

    cudaFuncSetAttribute(k2_mma, cudaFuncAttributeMaxDynamicSharedMemorySize, K2_SMEM);
    cudaFuncSetAttribute(k4f, cudaFuncAttributeMaxDynamicSharedMemorySize, K4_SMEM);

    k2_mma<<<128, 256, K2_SMEM>>>(x, conv_w, conv_b);
    k3_q<<<BB, 128>>>();
    k4f<<<SS / 128, 256, K4_SMEM>>>(memory);
    k5_topk<<<BB, 256>>>(memory);
    dim3 g6(128, BB);
    k6_add<<<g6, 256>>>(x, scale, out);
    (void)in_sizes; (void)n_in; (void)out_size;
}

// round 7
// speedup vs baseline: 1.5628x; 1.3917x over previous
#include <cuda_runtime.h>
#include <math.h>
#include <stdint.h>

#define BB 64
#define NN 4096
#define DD 128
#define SS 65536
#define KTOP 16
#define NCH 8                         // top-k scan chunks per b
#define CHSZ (SS / NCH)               // 8192

typedef unsigned long long ull;

// ---------------- scratch (device globals; allocation-free) ----------------
__device__ float g_qpart[BB * 2 * DD];   // per-CTA partial gelu sums
__device__ float g_qt[DD * BB];          // normalized q^T: [d][b]
__device__ float g_sim[(size_t)BB * SS]; // cosine sims                    (16 MB)
__device__ float g_proto[BB * DD];
__device__ float g_cand_v[BB * NCH * KTOP];
__device__ int   g_cand_i[BB * NCH * KTOP];

// ---------------- generic helpers ----------------
__device__ __forceinline__ ull ffma2(ull a, ull b, ull c) {
    ull d;
    asm("fma.rn.f32x2 %0, %1, %2, %3;" : "=l"(d) : "l"(a), "l"(b), "l"(c));
    return d;
}
__device__ __forceinline__ ull dup2(float x) {
    ull d;
    asm("mov.b64 %0, {%1, %1};" : "=l"(d) : "f"(x));
    return d;
}
__device__ __forceinline__ void unpack2(ull v, float& lo, float& hi) {
    asm("mov.b64 {%0, %1}, %2;" : "=f"(lo), "=f"(hi) : "l"(v));
}
__device__ __forceinline__ float gelu_exact(float z) {
    return 0.5f * z * (1.0f + erff(z * 0.70710678118654752f));
}
__device__ __forceinline__ float tf32r(float x) {
    float y;
    asm("cvt.rna.tf32.f32 %0, %1;" : "=f"(y) : "f"(x));
    return y;
}
__device__ __forceinline__ uint32_t smem_u32(const void* p) {
    uint32_t a;
    asm("{ .reg .u64 t; cvta.to.shared.u64 t, %1; cvt.u32.u64 %0, t; }" : "=r"(a) : "l"(p));
    return a;
}
__device__ __forceinline__ void cpa16(uint32_t dst, const void* src) {
    asm volatile("cp.async.cg.shared.global [%0], [%1], 16;" :: "r"(dst), "l"(src));
}
#define CP_COMMIT() asm volatile("cp.async.commit_group;" ::: "memory")

// tf32 m16n8k8 mma.sync (portable PTX; lowers to HMMA fallback on sm_103)
__device__ __forceinline__ void mma_tf32(float* c, uint32_t a0, uint32_t a1,
                                         uint32_t a2, uint32_t a3,
                                         uint32_t b0, uint32_t b1) {
    asm volatile(
        "mma.sync.aligned.m16n8k8.row.col.f32.tf32.tf32.f32 "
        "{%0,%1,%2,%3}, {%4,%5,%6,%7}, {%8,%9}, {%0,%1,%2,%3};"
        : "+f"(c[0]), "+f"(c[1]), "+f"(c[2]), "+f"(c[3])
        : "r"(a0), "r"(a1), "r"(a2), "r"(a3), "r"(b0), "r"(b1));
}

// ---------------- K2: tf32 mma.sync conv1d+GeLU+sum-over-n --------------
#define WSTR 132
#define ASTR 68
#define ABUF 8704                    // 128 * 68 floats
#define F_WHI  0
#define F_A    16896
#define F_BIAS 51712
#define F_RED  51840
#define K2_SMEM ((51840 + 256) * 4)  // 208384 bytes

__global__ void __launch_bounds__(256, 1) k2_mma(const float* __restrict__ x,
                                                 const float* __restrict__ w,
                                                 const float* __restrict__ bias) {
    extern __shared__ float sm[];
    float* ws_hi = sm + F_WHI;
    float* sbias = sm + F_BIAS;
    float* red   = sm + F_RED;
    uint32_t aB = smem_u32(sm + F_A);

    int tid = threadIdx.x, wid = tid >> 5, lane = tid & 31;
    int g = lane >> 2, kc = lane & 3;
    int cta = blockIdx.x, b = cta >> 1, half = cta & 1;
    const float* xb = x + ((size_t)b * NN + (size_t)half * 2048) * DD;

    for (int i = tid; i < 4096; i += 256) {
        float4 v = ((const float4*)w)[i];
        int e = i >> 5, c4 = (i & 31) * 4;
        float4 h;
        h.x = tf32r(v.x); h.y = tf32r(v.y); h.z = tf32r(v.z); h.w = tf32r(v.w);
        *(float4*)&ws_hi[e * WSTR + c4] = h;
    }
    if (tid < 128) sbias[tid] = bias[tid];

    int ew = (wid & 3) * 32;

    float c[4][4][4];
    #pragma unroll
    for (int mf = 0; mf < 4; ++mf)
        #pragma unroll
        for (int ef = 0; ef < 4; ++ef)
            #pragma unroll
            for (int q = 0; q < 4; ++q) c[mf][ef][q] = 0.f;
    float es[8];
    #pragma unroll
    for (int s = 0; s < 8; ++s) es[s] = 0.f;

    auto issue_load = [&](int gstep, int buf) {
        int t = gstep >> 1, h = gstep & 1;
        const float* base = xb + (size_t)t * (128 * DD) + h * 64;
        uint32_t dst0 = aB + (uint32_t)buf * (ABUF * 4);
        #pragma unroll
        for (int j = 0; j < 8; ++j) {
            int idx = j * 256 + tid;
            int row = idx >> 4, seg = idx & 15;
            cpa16(dst0 + (uint32_t)(row * ASTR + seg * 4) * 4,
                  base + (size_t)row * DD + seg * 4);
        }
    };

    issue_load(0, 0); CP_COMMIT();
    issue_load(1, 1); CP_COMMIT();
    __syncthreads();

    float bs[8];
    #pragma unroll
    for (int ef = 0; ef < 4; ++ef) {
        bs[ef * 2 + 0] = sbias[ew + ef * 8 + 2 * kc + 0];
        bs[ef * 2 + 1] = sbias[ew + ef * 8 + 2 * kc + 1];
    }

    int mrow = (wid >> 2) * 64 + g;

    #pragma unroll 1
    for (int step = 0; step < 32; ++step) {
        if (step < 30) {
            issue_load(step + 2, (step + 2) & 3); CP_COMMIT();
            asm volatile("cp.async.wait_group 2;" ::: "memory");
        } else if (step == 30) {
            asm volatile("cp.async.wait_group 1;" ::: "memory");
        } else {
            asm volatile("cp.async.wait_group 0;" ::: "memory");
        }
        __syncthreads();

        const float* A = sm + F_A + (step & 3) * ABUF;
        int kg0 = (step & 1) * 64;
        #pragma unroll
        for (int ks = 0; ks < 8; ++ks) {
            int k0 = ks * 8 + kc;
            uint32_t a[4][4];
            #pragma unroll
            for (int mf = 0; mf < 4; ++mf) {
                int r = mrow + mf * 16;
                a[mf][0] = __float_as_uint(A[r * ASTR + k0]);
                a[mf][1] = __float_as_uint(A[(r + 8) * ASTR + k0]);
                a[mf][2] = __float_as_uint(A[r * ASTR + k0 + 4]);
                a[mf][3] = __float_as_uint(A[(r + 8) * ASTR + k0 + 4]);
            }
            #pragma unroll
            for (int ef = 0; ef < 4; ++ef) {
                int e = ew + ef * 8 + g;
                uint32_t b0 = __float_as_uint(ws_hi[e * WSTR + kg0 + k0]);
                uint32_t b1 = __float_as_uint(ws_hi[e * WSTR + kg0 + k0 + 4]);
                #pragma unroll
                for (int mf = 0; mf < 4; ++mf)
                    mma_tf32(c[mf][ef], a[mf][0], a[mf][1], a[mf][2], a[mf][3], b0, b1);
            }
        }

        if ((step & 1) == 1) {
            #pragma unroll
            for (int mf = 0; mf < 4; ++mf)
                #pragma unroll
                for (int ef = 0; ef < 4; ++ef)
                    #pragma unroll
                    for (int q = 0; q < 4; ++q) {
                        int s = ef * 2 + (q & 1);
                        es[s] += gelu_exact(c[mf][ef][q] + bs[s]);
                        c[mf][ef][q] = 0.f;
                    }
        }
    }

    #pragma unroll
    for (int off = 16; off >= 4; off >>= 1)
        #pragma unroll
        for (int s = 0; s < 8; ++s)
            es[s] += __shfl_xor_sync(0xffffffffu, es[s], off);
    __syncthreads();
    if (g == 0) {
        #pragma unroll
        for (int s = 0; s < 8; ++s) {
            int ecol = ew + (s >> 1) * 8 + 2 * kc + (s & 1);
            red[(wid >> 2) * 128 + ecol] = es[s];
        }
    }
    __syncthreads();
    if (tid < 128)
        g_qpart[(b * 2 + half) * 128 + tid] = red[tid] + red[128 + tid];
}

// ---------------- K3: finalize q + normalize + transpose ----------------
__global__ void k3_q() {
    int b = blockIdx.x, e = threadIdx.x;
    float q = g_qpart[b * 256 + e] + g_qpart[b * 256 + 128 + e];
    __shared__ float sr[128];
    sr[e] = q * q;
    __syncthreads();
    for (int off = 64; off; off >>= 1) {
        if (e < off) sr[e] += sr[e + off];
        __syncthreads();
    }
    float inv = 1.0f / fmaxf(sqrtf(sr[0]), 1e-12f);
    g_qt[e * 64 + b] = q * inv;
}

// ---------------- K4f: fused normalize + sim GEMM -----------------------
#define S4_QS  0
#define S4_MT  8192
#define S4_TL  24576
#define S4_INV 32832
#define K4_SMEM ((32832 + 64) * 4)   // 131584 bytes

__global__ void __launch_bounds__(256, 1) k4f(const float* __restrict__ mem) {
    extern __shared__ float s4[];
    float* qs   = s4 + S4_QS;
    float* mt   = s4 + S4_MT;
    float* tile = s4 + S4_TL;
    float* inv  = s4 + S4_INV;
    int tid = threadIdx.x;
    int s0 = blockIdx.x * 128;

    for (int i = tid; i < 8192; i += 256) qs[i] = g_qt[i];

    #pragma unroll 1
    for (int half = 0; half < 2; ++half) {
        int c = tid & 31, r0 = tid >> 5;
        #pragma unroll
        for (int it = 0; it < 8; ++it) {
            int r = r0 + it * 8;
            float4 v = *(const float4*)&mem[(size_t)(s0 + half * 64 + r) * 128 + c * 4];
            tile[r * 129 + c * 4 + 0] = v.x; tile[r * 129 + c * 4 + 1] = v.y;
            tile[r * 129 + c * 4 + 2] = v.z; tile[r * 129 + c * 4 + 3] = v.w;
        }
        __syncthreads();
        if (tid < 64) {
            float acc = 0.f;
            #pragma unroll 8
            for (int k = 0; k < 128; ++k) { float t = tile[tid * 129 + k]; acc = fmaf(t, t, acc); }
            inv[tid] = 1.0f / fmaxf(sqrtf(acc), 1e-12f);
        }
        __syncthreads();
        int r = tid & 63, kg = tid >> 6;
        float iv = inv[r];
        #pragma unroll
        for (int it = 0; it < 32; ++it) {
            int k = kg + it * 4;
            mt[k * 128 + half * 64 + r] = tile[r * 129 + k] * iv;
        }
        __syncthreads();
    }

    int tm = tid >> 4, tn = tid & 15;
    ull acc[4][4];
    #pragma unroll
    for (int i = 0; i < 4; ++i)
        #pragma unroll
        for (int j = 0; j < 4; ++j) acc[i][j] = 0ull;

    #pragma unroll 8
    for (int k = 0; k < 128; ++k) {
        float4 av = *(const float4*)&qs[k * 64 + tm * 4];
        ull a0 = dup2(av.x), a1 = dup2(av.y), a2 = dup2(av.z), a3 = dup2(av.w);
        const float* mrow = mt + k * 128;
        #pragma unroll
        for (int gg = 0; gg < 2; ++gg) {
            ulonglong2 bv = *(const ulonglong2*)(mrow + (tn + gg * 16) * 4);
            acc[0][gg * 2 + 0] = ffma2(a0, bv.x, acc[0][gg * 2 + 0]);
            acc[0][gg * 2 + 1] = ffma2(a0, bv.y, acc[0][gg * 2 + 1]);
            acc[1][gg * 2 + 0] = ffma2(a1, bv.x, acc[1][gg * 2 + 0]);
            acc[1][gg * 2 + 1] = ffma2(a1, bv.y, acc[1][gg * 2 + 1]);
            acc[2][gg * 2 + 0] = ffma2(a2, bv.x, acc[2][gg * 2 + 0]);
            acc[2][gg * 2 + 1] = ffma2(a2, bv.y, acc[2][gg * 2 + 1]);
            acc[3][gg * 2 + 0] = ffma2(a3, bv.x, acc[3][gg * 2 + 0]);
            acc[3][gg * 2 + 1] = ffma2(a3, bv.y, acc[3][gg * 2 + 1]);
        }
    }
    #pragma unroll
    for (int i = 0; i < 4; ++i) {
        int b = tm * 4 + i;
        #pragma unroll
        for (int gg = 0; gg < 2; ++gg) {
            float4 o;
            unpack2(acc[i][gg * 2 + 0], o.x, o.y);
            unpack2(acc[i][gg * 2 + 1], o.z, o.w);
            *(float4*)&g_sim[(size_t)b * SS + s0 + (tn + gg * 16) * 4] = o;
        }
    }
}

// ---------------- K5a: per-chunk exact top-16 ---------------------------
// grid (NCH, BB), block 256. Per-thread top-16 over 32 vals, warp shuffle
// argmax x16 rounds, warp0 reduces 8x16 -> chunk top-16.
__global__ void __launch_bounds__(256) k5a() {
    int b = blockIdx.y, ch = blockIdx.x;
    int tid = threadIdx.x, wid = tid >> 5, lane = tid & 31;
    __shared__ float wv[8 * KTOP];
    __shared__ int   wi[8 * KTOP];

    const float4* rowv = (const float4*)(g_sim + (size_t)b * SS + (size_t)ch * CHSZ);

    float vs[KTOP]; int is[KTOP];
    #pragma unroll
    for (int j = 0; j < KTOP; ++j) { vs[j] = -1e30f; is[j] = 0; }
    float mn = -1e30f; int mj = 0;

    #pragma unroll
    for (int it = 0; it < 8; ++it) {
        int f = it * 256 + tid;          // float4 index within chunk (0..2047)
        float4 v = rowv[f];
        float vm = fmaxf(fmaxf(v.x, v.y), fmaxf(v.z, v.w));
        if (vm > mn) {
            float vals[4] = {v.x, v.y, v.z, v.w};
            int sb = ch * CHSZ + f * 4;
            #pragma unroll
            for (int j = 0; j < 4; ++j) {
                if (vals[j] > mn) {
                    #pragma unroll
                    for (int jj = 0; jj < KTOP; ++jj)
                        if (jj == mj) { vs[jj] = vals[j]; is[jj] = sb + j; }
                    mn = vs[0]; mj = 0;
                    #pragma unroll
                    for (int jj = 1; jj < KTOP; ++jj)
                        if (vs[jj] < mn) { mn = vs[jj]; mj = jj; }
                }
            }
        }
    }

    // warp-level: 16 rounds of argmax over lanes' locals
    #pragma unroll 1
    for (int r = 0; r < KTOP; ++r) {
        float mv = vs[0]; int lm = 0;
        #pragma unroll
        for (int j = 1; j < KTOP; ++j) if (vs[j] > mv) { mv = vs[j]; lm = j; }
        int myidx = is[lm];
        float bv = mv; int bl = lane;
        #pragma unroll
        for (int off = 16; off; off >>= 1) {
            float ov = __shfl_xor_sync(0xffffffffu, bv, off);
            int ol = __shfl_xor_sync(0xffffffffu, bl, off);
            if (ov > bv || (ov == bv && ol < bl)) { bv = ov; bl = ol; }
        }
        int widx = __shfl_sync(0xffffffffu, myidx, bl);
        if (lane == bl) {
            #pragma unroll
            for (int jj = 0; jj < KTOP; ++jj) if (jj == lm) vs[jj] = -1e30f;
        }
        if (lane == 0) { wv[wid * KTOP + r] = bv; wi[wid * KTOP + r] = widx; }
    }
    __syncthreads();

    // warp 0 reduces 128 candidates -> 16
    if (wid == 0) {
        float v4[4]; int i4[4];
        #pragma unroll
        for (int j = 0; j < 4; ++j) { v4[j] = wv[lane * 4 + j]; i4[j] = wi[lane * 4 + j]; }
        #pragma unroll 1
        for (int r = 0; r < KTOP; ++r) {
            float mv = v4[0]; int lm = 0;
            #pragma unroll
            for (int j = 1; j < 4; ++j) if (v4[j] > mv) { mv = v4[j]; lm = j; }
            int myidx = i4[lm];
            float bv = mv; int bl = lane;
            #pragma unroll
            for (int off = 16; off; off >>= 1) {
                float ov = __shfl_xor_sync(0xffffffffu, bv, off);
                int ol = __shfl_xor_sync(0xffffffffu, bl, off);
                if (ov > bv || (ov == bv && ol < bl)) { bv = ov; bl = ol; }
            }
            int widx = __shfl_sync(0xffffffffu, myidx, bl);
            if (lane == bl) {
                #pragma unroll
                for (int jj = 0; jj < 4; ++jj) if (jj == lm) v4[jj] = -1e30f;
            }
            if (lane == 0) {
                g_cand_v[(b * NCH + ch) * KTOP + r] = bv;
                g_cand_i[(b * NCH + ch) * KTOP + r] = widx;
            }
        }
    }
}

// ---------------- K5b: final top-16 + softmax + proto gather ------------
__global__ void __launch_bounds__(128) k5b(const float* __restrict__ mem) {
    int b = blockIdx.x;
    int tid = threadIdx.x, wid = tid >> 5, lane = tid & 31;
    __shared__ float selv[KTOP];
    __shared__ int   seli[KTOP];
    __shared__ float attn[KTOP];

    if (wid == 0) {
        float v4[4]; int i4[4];
        #pragma unroll
        for (int j = 0; j < 4; ++j) {
            v4[j] = g_cand_v[b * (NCH * KTOP) + lane * 4 + j];
            i4[j] = g_cand_i[b * (NCH * KTOP) + lane * 4 + j];
        }
        #pragma unroll 1
        for (int r = 0; r < KTOP; ++r) {
            float mv = v4[0]; int lm = 0;
            #pragma unroll
            for (int j = 1; j < 4; ++j) if (v4[j] > mv) { mv = v4[j]; lm = j; }
            int myidx = i4[lm];
            float bv = mv; int bl = lane;
            #pragma unroll
            for (int off = 16; off; off >>= 1) {
                float ov = __shfl_xor_sync(0xffffffffu, bv, off);
                int ol = __shfl_xor_sync(0xffffffffu, bl, off);
                if (ov > bv || (ov == bv && ol < bl)) { bv = ov; bl = ol; }
            }
            int widx = __shfl_sync(0xffffffffu, myidx, bl);
            if (lane == bl) {
                #pragma unroll
                for (int jj = 0; jj < 4; ++jj) if (jj == lm) v4[jj] = -1e30f;
            }
            if (lane == 0) { selv[r] = bv; seli[r] = widx; }
        }
        if (lane == 0) {
            float mx = selv[0];
            float e[KTOP], ssum = 0.f;
            #pragma unroll
            for (int k = 0; k < KTOP; ++k) { e[k] = expf(selv[k] - mx); ssum += e[k]; }
            #pragma unroll
            for (int k = 0; k < KTOP; ++k) attn[k] = e[k] / ssum;
        }
    }
    __syncthreads();

    float acc = 0.f;
    #pragma unroll
    for (int k = 0; k < KTOP; ++k)
        acc = fmaf(attn[k], mem[(size_t)seli[k] * 128 + tid], acc);
    g_proto[b * 128 + tid] = acc;
}

// ---------------- K6: out = x + scale * proto ---------------------------
__global__ void __launch_bounds__(256) k6_add(const float* __restrict__ x,
                                              const float* __restrict__ scale_p,
                                              float* __restrict__ out) {
    __shared__ float pr[128];
    __shared__ float sc;
    int b = blockIdx.y;
    if (threadIdx.x < 128) pr[threadIdx.x] = g_proto[b * 128 + threadIdx.x];
    if (threadIdx.x == 0) sc = *scale_p;
    __syncthreads();

    float s = sc;
    const float4* xv = (const float4*)x;
    float4* ov = (float4*)out;
    size_t f0 = ((size_t)b * (NN * DD) + (size_t)blockIdx.x * 4096) >> 2;
    #pragma unroll
    for (int it = 0; it < 4; ++it) {
        size_t f = f0 + it * 256 + threadIdx.x;
        float4 v = xv[f];
        int d4 = (int)(f & 31);
        const float* p = &pr[d4 * 4];
        v.x = fmaf(s, p[0], v.x);
        v.y = fmaf(s, p[1], v.y);
        v.z = fmaf(s, p[2], v.z);
        v.w = fmaf(s, p[3], v.w);
        ov[f] = v;
    }
}

// ---------------- launch -------------------------------------------------
extern "C" void kernel_launch(void* const* d_in, const int* in_sizes, int n_in,
                              void* d_out, int out_size) {
    const float* x      = (const float*)d_in[0];
    const float* conv_w = (const float*)d_in[1];
    const float* conv_b = (const float*)d_in[2];
    const float* memory = (const float*)d_in[3];
    const float* scale  = (const float*)d_in[4];
    float* out = (float*)d_out;

    cudaFuncSetAttribute(k2_mma, cudaFuncAttributeMaxDynamicSharedMemorySize, K2_SMEM);
    cudaFuncSetAttribute(k4f, cudaFuncAttributeMaxDynamicSharedMemorySize, K4_SMEM);

    k2_mma<<<128, 256, K2_SMEM>>>(x, conv_w, conv_b);
    k3_q<<<BB, 128>>>();
    k4f<<<SS / 128, 256, K4_SMEM>>>(memory);
    dim3 g5a(NCH, BB);
    k5a<<<g5a, 256>>>();
    k5b<<<BB, 128>>>(memory);
    dim3 g6(128, BB);
    k6_add<<<g6, 256>>>(x, scale, out);
    (void)in_sizes; (void)n_in; (void)out_size;
}

// round 8
// speedup vs baseline: 1.8125x; 1.1598x over previous
#include <cuda_runtime.h>
#include <math.h>
#include <stdint.h>

#define BB 64
#define NN 4096
#define DD 128
#define SS 65536
#define KTOP 16
#define NCH 16                        // top-k scan chunks per b
#define CHSZ (SS / NCH)               // 4096

typedef unsigned long long ull;

// ---------------- scratch (device globals; allocation-free) ----------------
__device__ float g_qpart[BB * 2 * DD];   // per-CTA partial gelu sums
__device__ float g_qt[DD * BB];          // normalized q^T: [d][b]
__device__ float g_sim[(size_t)BB * SS]; // cosine sims                    (16 MB)
__device__ float g_proto[BB * DD];
__device__ float g_cand_v[BB * NCH * KTOP];
__device__ int   g_cand_i[BB * NCH * KTOP];

// ---------------- generic helpers ----------------
__device__ __forceinline__ ull ffma2(ull a, ull b, ull c) {
    ull d;
    asm("fma.rn.f32x2 %0, %1, %2, %3;" : "=l"(d) : "l"(a), "l"(b), "l"(c));
    return d;
}
__device__ __forceinline__ ull dup2(float x) {
    ull d;
    asm("mov.b64 %0, {%1, %1};" : "=l"(d) : "f"(x));
    return d;
}
__device__ __forceinline__ void unpack2(ull v, float& lo, float& hi) {
    asm("mov.b64 {%0, %1}, %2;" : "=f"(lo), "=f"(hi) : "l"(v));
}
__device__ __forceinline__ float gelu_exact(float z) {
    return 0.5f * z * (1.0f + erff(z * 0.70710678118654752f));
}
// pack two fp32 -> bf16x2 (lo = first arg, hi = second)
__device__ __forceinline__ uint32_t bpack(float lo, float hi) {
    uint32_t r;
    asm("cvt.rn.bf16x2.f32 %0, %1, %2;" : "=r"(r) : "f"(hi), "f"(lo));
    return r;
}
__device__ __forceinline__ uint32_t smem_u32(const void* p) {
    uint32_t a;
    asm("{ .reg .u64 t; cvta.to.shared.u64 t, %1; cvt.u32.u64 %0, t; }" : "=r"(a) : "l"(p));
    return a;
}

// bf16 m16n8k16 mma.sync
__device__ __forceinline__ void mma_bf16(float* c, uint32_t a0, uint32_t a1,
                                         uint32_t a2, uint32_t a3,
                                         uint32_t b0, uint32_t b1) {
    asm volatile(
        "mma.sync.aligned.m16n8k16.row.col.f32.bf16.bf16.f32 "
        "{%0,%1,%2,%3}, {%4,%5,%6,%7}, {%8,%9}, {%0,%1,%2,%3};"
        : "+f"(c[0]), "+f"(c[1]), "+f"(c[2]), "+f"(c[3])
        : "r"(a0), "r"(a1), "r"(a2), "r"(a3), "r"(b0), "r"(b1));
}

// ---------------- K2: bf16 mma.sync conv1d+GeLU+sum-over-n --------------
// 128 CTAs: cta = (b, half). 16 tiles of 128 positions = 32 k-half steps.
// x converted fp32->bf16 in-register (LDG->cvt->STS); 3-buffer smem ring.
#define WS16 136                     // bf16 per W row (128 + 8 pad)
#define AS16 72                      // bf16 per A row (64 + 8 pad)
#define AB16 (128 * AS16)            // 9216 bf16 per A buffer (18432 B)
#define O_W    0                     // 128*136*2 = 34816 B
#define O_A    34816                 // 3 * 18432 = 55296 B
#define O_BIAS 90112                 // 512 B
#define O_RED  90624                 // 1024 B
#define K2_SMEM 91648

__global__ void __launch_bounds__(256, 1) k2_mma(const float* __restrict__ x,
                                                 const float* __restrict__ w,
                                                 const float* __restrict__ bias) {
    extern __shared__ char smc[];
    uint16_t* ws    = (uint16_t*)(smc + O_W);
    uint16_t* ab    = (uint16_t*)(smc + O_A);
    float*    sbias = (float*)(smc + O_BIAS);
    float*    red   = (float*)(smc + O_RED);

    int tid = threadIdx.x, wid = tid >> 5, lane = tid & 31;
    int g = lane >> 2, kc = lane & 3;
    int cta = blockIdx.x, b = cta >> 1, half = cta & 1;
    const float* xb = x + ((size_t)b * NN + (size_t)half * 2048) * DD;

    // ---- stage W as bf16 [e][k] ----
    for (int i = tid; i < 4096; i += 256) {      // float4 over [128e][32]
        float4 v = ((const float4*)w)[i];
        int e = i >> 5, d0 = (i & 31) * 4;
        uint2 p = make_uint2(bpack(v.x, v.y), bpack(v.z, v.w));
        *(uint2*)&ws[e * WS16 + d0] = p;
    }
    if (tid < 128) sbias[tid] = bias[tid];

    int ew = (wid & 3) * 32;

    float c[4][4][4];
    #pragma unroll
    for (int mf = 0; mf < 4; ++mf)
        #pragma unroll
        for (int ef = 0; ef < 4; ++ef)
            #pragma unroll
            for (int q = 0; q < 4; ++q) c[mf][ef][q] = 0.f;
    float es[8];
    #pragma unroll
    for (int s = 0; s < 8; ++s) es[s] = 0.f;

    float4 r8[8];
    auto ldg = [&](int gstep) {
        int t = gstep >> 1, h = gstep & 1;
        const float* base = xb + (size_t)t * (128 * DD) + h * 64;
        #pragma unroll
        for (int j = 0; j < 8; ++j) {
            int idx = j * 256 + tid;             // 0..2047
            int row = idx >> 4, seg = idx & 15;
            r8[j] = *(const float4*)(base + (size_t)row * DD + seg * 4);
        }
    };
    auto sts = [&](int buf) {
        uint16_t* d = ab + buf * AB16;
        #pragma unroll
        for (int j = 0; j < 8; ++j) {
            int idx = j * 256 + tid;
            int row = idx >> 4, seg = idx & 15;
            uint2 p = make_uint2(bpack(r8[j].x, r8[j].y), bpack(r8[j].z, r8[j].w));
            *(uint2*)&d[row * AS16 + seg * 4] = p;
        }
    };

    ldg(0); sts(0);
    ldg(1);
    __syncthreads();                 // W + bias + buf0 visible

    float bs[8];
    #pragma unroll
    for (int ef = 0; ef < 4; ++ef) {
        bs[ef * 2 + 0] = sbias[ew + ef * 8 + 2 * kc + 0];
        bs[ef * 2 + 1] = sbias[ew + ef * 8 + 2 * kc + 1];
    }

    int mrow = (wid >> 2) * 64 + g;

    #pragma unroll 1
    for (int step = 0; step < 32; ++step) {
        if (step < 31) sts((step + 1) % 3);      // regs for step+1 -> ring
        if (step < 30) ldg(step + 2);            // prefetch step+2
        __syncthreads();

        const uint16_t* A = ab + (step % 3) * AB16;
        int kg0 = (step & 1) * 64;               // k offset into W
        #pragma unroll
        for (int ks = 0; ks < 4; ++ks) {
            int kb = ks * 16;
            uint32_t a[4][4];
            #pragma unroll
            for (int mf = 0; mf < 4; ++mf) {
                int r = mrow + mf * 16;
                a[mf][0] = *(const uint32_t*)&A[r * AS16 + kb + 2 * kc];
                a[mf][1] = *(const uint32_t*)&A[(r + 8) * AS16 + kb + 2 * kc];
                a[mf][2] = *(const uint32_t*)&A[r * AS16 + kb + 2 * kc + 8];
                a[mf][3] = *(const uint32_t*)&A[(r + 8) * AS16 + kb + 2 * kc + 8];
            }
            #pragma unroll
            for (int ef = 0; ef < 4; ++ef) {
                int e = ew + ef * 8 + g;
                uint32_t b0 = *(const uint32_t*)&ws[e * WS16 + kg0 + kb + 2 * kc];
                uint32_t b1 = *(const uint32_t*)&ws[e * WS16 + kg0 + kb + 2 * kc + 8];
                #pragma unroll
                for (int mf = 0; mf < 4; ++mf)
                    mma_bf16(c[mf][ef], a[mf][0], a[mf][1], a[mf][2], a[mf][3], b0, b1);
            }
        }

        if ((step & 1) == 1) {                   // tile done: gelu + accumulate
            #pragma unroll
            for (int mf = 0; mf < 4; ++mf)
                #pragma unroll
                for (int ef = 0; ef < 4; ++ef)
                    #pragma unroll
                    for (int q = 0; q < 4; ++q) {
                        int s = ef * 2 + (q & 1);
                        es[s] += gelu_exact(c[mf][ef][q] + bs[s]);
                        c[mf][ef][q] = 0.f;
                    }
        }
    }

    #pragma unroll
    for (int off = 16; off >= 4; off >>= 1)
        #pragma unroll
        for (int s = 0; s < 8; ++s)
            es[s] += __shfl_xor_sync(0xffffffffu, es[s], off);
    __syncthreads();
    if (g == 0) {
        #pragma unroll
        for (int s = 0; s < 8; ++s) {
            int ecol = ew + (s >> 1) * 8 + 2 * kc + (s & 1);
            red[(wid >> 2) * 128 + ecol] = es[s];
        }
    }
    __syncthreads();
    if (tid < 128)
        g_qpart[(b * 2 + half) * 128 + tid] = red[tid] + red[128 + tid];
}

// ---------------- K3: finalize q + normalize + transpose ----------------
__global__ void k3_q() {
    int b = blockIdx.x, e = threadIdx.x;
    float q = g_qpart[b * 256 + e] + g_qpart[b * 256 + 128 + e];
    __shared__ float sr[128];
    sr[e] = q * q;
    __syncthreads();
    for (int off = 64; off; off >>= 1) {
        if (e < off) sr[e] += sr[e + off];
        __syncthreads();
    }
    float inv = 1.0f / fmaxf(sqrtf(sr[0]), 1e-12f);
    g_qt[e * 64 + b] = q * inv;
}

// ---------------- K4f: fused normalize + sim GEMM -----------------------
#define S4_QS  0
#define S4_MT  8192
#define S4_TL  24576
#define S4_INV 32832
#define K4_SMEM ((32832 + 64) * 4)   // 131584 bytes

__global__ void __launch_bounds__(256, 1) k4f(const float* __restrict__ mem) {
    extern __shared__ float s4[];
    float* qs   = s4 + S4_QS;
    float* mt   = s4 + S4_MT;
    float* tile = s4 + S4_TL;
    float* inv  = s4 + S4_INV;
    int tid = threadIdx.x;
    int s0 = blockIdx.x * 128;

    for (int i = tid; i < 8192; i += 256) qs[i] = g_qt[i];

    #pragma unroll 1
    for (int half = 0; half < 2; ++half) {
        int c = tid & 31, r0 = tid >> 5;
        #pragma unroll
        for (int it = 0; it < 8; ++it) {
            int r = r0 + it * 8;
            float4 v = *(const float4*)&mem[(size_t)(s0 + half * 64 + r) * 128 + c * 4];
            tile[r * 129 + c * 4 + 0] = v.x; tile[r * 129 + c * 4 + 1] = v.y;
            tile[r * 129 + c * 4 + 2] = v.z; tile[r * 129 + c * 4 + 3] = v.w;
        }
        __syncthreads();
        if (tid < 64) {
            float acc = 0.f;
            #pragma unroll 8
            for (int k = 0; k < 128; ++k) { float t = tile[tid * 129 + k]; acc = fmaf(t, t, acc); }
            inv[tid] = 1.0f / fmaxf(sqrtf(acc), 1e-12f);
        }
        __syncthreads();
        int r = tid & 63, kg = tid >> 6;
        float iv = inv[r];
        #pragma unroll
        for (int it = 0; it < 32; ++it) {
            int k = kg + it * 4;
            mt[k * 128 + half * 64 + r] = tile[r * 129 + k] * iv;
        }
        __syncthreads();
    }

    int tm = tid >> 4, tn = tid & 15;
    ull acc[4][4];
    #pragma unroll
    for (int i = 0; i < 4; ++i)
        #pragma unroll
        for (int j = 0; j < 4; ++j) acc[i][j] = 0ull;

    #pragma unroll 8
    for (int k = 0; k < 128; ++k) {
        float4 av = *(const float4*)&qs[k * 64 + tm * 4];
        ull a0 = dup2(av.x), a1 = dup2(av.y), a2 = dup2(av.z), a3 = dup2(av.w);
        const float* mrow = mt + k * 128;
        #pragma unroll
        for (int gg = 0; gg < 2; ++gg) {
            ulonglong2 bv = *(const ulonglong2*)(mrow + (tn + gg * 16) * 4);
            acc[0][gg * 2 + 0] = ffma2(a0, bv.x, acc[0][gg * 2 + 0]);
            acc[0][gg * 2 + 1] = ffma2(a0, bv.y, acc[0][gg * 2 + 1]);
            acc[1][gg * 2 + 0] = ffma2(a1, bv.x, acc[1][gg * 2 + 0]);
            acc[1][gg * 2 + 1] = ffma2(a1, bv.y, acc[1][gg * 2 + 1]);
            acc[2][gg * 2 + 0] = ffma2(a2, bv.x, acc[2][gg * 2 + 0]);
            acc[2][gg * 2 + 1] = ffma2(a2, bv.y, acc[2][gg * 2 + 1]);
            acc[3][gg * 2 + 0] = ffma2(a3, bv.x, acc[3][gg * 2 + 0]);
            acc[3][gg * 2 + 1] = ffma2(a3, bv.y, acc[3][gg * 2 + 1]);
        }
    }
    #pragma unroll
    for (int i = 0; i < 4; ++i) {
        int b = tm * 4 + i;
        #pragma unroll
        for (int gg = 0; gg < 2; ++gg) {
            float4 o;
            unpack2(acc[i][gg * 2 + 0], o.x, o.y);
            unpack2(acc[i][gg * 2 + 1], o.z, o.w);
            *(float4*)&g_sim[(size_t)b * SS + s0 + (tn + gg * 16) * 4] = o;
        }
    }
}

// ---------------- K5a: exact threshold top-16 per chunk -----------------
// T = 16th largest of per-thread maxes (provably <= v16). Survivors >= T
// are collected (capacity = full chunk -> provably no overflow), then 16
// exact argmax rounds (tie-break: smaller global index -> deterministic).
__global__ void __launch_bounds__(256) k5a() {
    __shared__ float cv[CHSZ];
    __shared__ int   ci[CHSZ];
    __shared__ float tmax[256];
    __shared__ float s_thr;
    __shared__ int   s_cnt;

    int b = blockIdx.y, ch = blockIdx.x;
    int tid = threadIdx.x, lane = tid & 31;
    const float4* rowv = (const float4*)(g_sim + (size_t)b * SS + (size_t)ch * CHSZ);

    float4 v4[4];
    float m = -1e30f;
    #pragma unroll
    for (int it = 0; it < 4; ++it) {
        v4[it] = rowv[it * 256 + tid];
        m = fmaxf(m, fmaxf(fmaxf(v4[it].x, v4[it].y), fmaxf(v4[it].z, v4[it].w)));
    }
    tmax[tid] = m;
    if (tid == 0) s_cnt = 0;
    __syncthreads();

    if (tid < 32) {                  // warp0: 16th largest of 256 maxes
        float lv[8];
        #pragma unroll
        for (int j = 0; j < 8; ++j) lv[j] = tmax[lane * 8 + j];
        float T = 0.f;
        #pragma unroll 1
        for (int r = 0; r < KTOP; ++r) {
            float mv = lv[0]; int lm = 0;
            #pragma unroll
            for (int j = 1; j < 8; ++j) if (lv[j] > mv) { mv = lv[j]; lm = j; }
            float bv = mv; int bl = lane;
            #pragma unroll
            for (int off = 16; off; off >>= 1) {
                float ov = __shfl_xor_sync(0xffffffffu, bv, off);
                int ol = __shfl_xor_sync(0xffffffffu, bl, off);
                if (ov > bv || (ov == bv && ol < bl)) { bv = ov; bl = ol; }
            }
            if (lane == bl) {
                #pragma unroll
                for (int j = 0; j < 8; ++j) if (j == lm) lv[j] = -1e30f;
            }
            T = bv;
        }
        if (lane == 0) s_thr = T;
    }
    __syncthreads();

    float T = s_thr;
    int base = ch * CHSZ;
    #pragma unroll
    for (int it = 0; it < 4; ++it) {
        float vals[4] = {v4[it].x, v4[it].y, v4[it].z, v4[it].w};
        #pragma unroll
        for (int j = 0; j < 4; ++j) {
            if (vals[j] >= T) {
                int p = atomicAdd(&s_cnt, 1);
                cv[p] = vals[j];
                ci[p] = base + (it * 256 + tid) * 4 + j;
            }
        }
    }
    __syncthreads();

    int n = s_cnt;
    if (tid < 32) {                  // 16 exact argmax rounds over survivors
        #pragma unroll 1
        for (int r = 0; r < KTOP; ++r) {
            float mv = -1e30f; int gi = 0x7fffffff; int mi = 0;
            for (int i = lane; i < n; i += 32) {
                float v = cv[i]; int idx = ci[i];
                if (v > mv || (v == mv && idx < gi)) { mv = v; gi = idx; mi = i; }
            }
            float bv = mv; int bgi = gi; int bmi = mi;
            #pragma unroll
            for (int off = 16; off; off >>= 1) {
                float ov  = __shfl_xor_sync(0xffffffffu, bv, off);
                int   ogi = __shfl_xor_sync(0xffffffffu, bgi, off);
                int   omi = __shfl_xor_sync(0xffffffffu, bmi, off);
                if (ov > bv || (ov == bv && ogi < bgi)) { bv = ov; bgi = ogi; bmi = omi; }
            }
            if (lane == 0) {
                g_cand_v[(b * NCH + ch) * KTOP + r] = bv;
                g_cand_i[(b * NCH + ch) * KTOP + r] = bgi;
                cv[bmi] = -1e30f;
            }
            __syncwarp();
        }
    }
}

// ---------------- K5b: final top-16 + softmax + proto gather ------------
__global__ void __launch_bounds__(128) k5b(const float* __restrict__ mem) {
    int b = blockIdx.x;
    int tid = threadIdx.x, lane = tid & 31;
    __shared__ float selv[KTOP];
    __shared__ int   seli[KTOP];
    __shared__ float attn[KTOP];

    if (tid < 32) {
        float lv[8]; int li[8];
        #pragma unroll
        for (int j = 0; j < 8; ++j) {
            lv[j] = g_cand_v[b * (NCH * KTOP) + lane * 8 + j];
            li[j] = g_cand_i[b * (NCH * KTOP) + lane * 8 + j];
        }
        #pragma unroll 1
        for (int r = 0; r < KTOP; ++r) {
            float mv = lv[0]; int gi = li[0]; int lm = 0;
            #pragma unroll
            for (int j = 1; j < 8; ++j)
                if (lv[j] > mv || (lv[j] == mv && li[j] < gi)) { mv = lv[j]; gi = li[j]; lm = j; }
            float bv = mv; int bgi = gi; int bl = lane;
            #pragma unroll
            for (int off = 16; off; off >>= 1) {
                float ov  = __shfl_xor_sync(0xffffffffu, bv, off);
                int   ogi = __shfl_xor_sync(0xffffffffu, bgi, off);
                int   ol  = __shfl_xor_sync(0xffffffffu, bl, off);
                if (ov > bv || (ov == bv && ogi < bgi)) { bv = ov; bgi = ogi; bl = ol; }
            }
            if (lane == bl) {
                #pragma unroll
                for (int j = 0; j < 8; ++j) if (j == lm) lv[j] = -1e30f;
            }
            if (lane == 0) { selv[r] = bv; seli[r] = bgi; }
        }
        if (lane == 0) {
            float mx = selv[0];
            float e[KTOP], ssum = 0.f;
            #pragma unroll
            for (int k = 0; k < KTOP; ++k) { e[k] = expf(selv[k] - mx); ssum += e[k]; }
            #pragma unroll
            for (int k = 0; k < KTOP; ++k) attn[k] = e[k] / ssum;
        }
    }
    __syncthreads();

    float acc = 0.f;
    #pragma unroll
    for (int k = 0; k < KTOP; ++k)
        acc = fmaf(attn[k], mem[(size_t)seli[k] * 128 + tid], acc);
    g_proto[b * 128 + tid] = acc;
}

// ---------------- K6: out = x + scale * proto ---------------------------
__global__ void __launch_bounds__(256) k6_add(const float* __restrict__ x,
                                              const float* __restrict__ scale_p,
                                              float* __restrict__ out) {
    __shared__ float pr[128];
    __shared__ float sc;
    int b = blockIdx.y;
    if (threadIdx.x < 128) pr[threadIdx.x] = g_proto[b * 128 + threadIdx.x];
    if (threadIdx.x == 0) sc = *scale_p;
    __syncthreads();

    float s = sc;
    const float4* xv = (const float4*)x;
    float4* ov = (float4*)out;
    size_t f0 = ((size_t)b * (NN * DD) + (size_t)blockIdx.x * 4096) >> 2;
    #pragma unroll
    for (int it = 0; it < 4; ++it) {
        size_t f = f0 + it * 256 + threadIdx.x;
        float4 v = xv[f];
        int d4 = (int)(f & 31);
        const float* p = &pr[d4 * 4];
        v.x = fmaf(s, p[0], v.x);
        v.y = fmaf(s, p[1], v.y);
        v.z = fmaf(s, p[2], v.z);
        v.w = fmaf(s, p[3], v.w);
        ov[f] = v;
    }
}

// ---------------- launch -------------------------------------------------
extern "C" void kernel_launch(void* const* d_in, const int* in_sizes, int n_in,
                              void* d_out, int out_size) {
    const float* x      = (const float*)d_in[0];
    const float* conv_w = (const float*)d_in[1];
    const float* conv_b = (const float*)d_in[2];
    const float* memory = (const float*)d_in[3];
    const float* scale  = (const float*)d_in[4];
    float* out = (float*)d_out;

    cudaFuncSetAttribute(k2_mma, cudaFuncAttributeMaxDynamicSharedMemorySize, K2_SMEM);
    cudaFuncSetAttribute(k4f, cudaFuncAttributeMaxDynamicSharedMemorySize, K4_SMEM);

    k2_mma<<<128, 256, K2_SMEM>>>(x, conv_w, conv_b);
    k3_q<<<BB, 128>>>();
    k4f<<<SS / 128, 256, K4_SMEM>>>(memory);
    dim3 g5a(NCH, BB);
    k5a<<<g5a, 256>>>();
    k5b<<<BB, 128>>>(memory);
    dim3 g6(128, BB);
    k6_add<<<g6, 256>>>(x, scale, out);
    (void)in_sizes; (void)n_in; (void)out_size;
}